// round 8
// baseline (speedup 1.0000x reference)
#include <cuda_runtime.h>
#include <cstdint>

#define HW 1024
#define PLANE (HW * HW)
#define BMAX 16

static constexpr float CW0 = 1.0f / 16.0f;
static constexpr float CW1 = 1.0f / 4.0f;
static constexpr float CW2 = 3.0f / 8.0f;

// Ping-pong scratch for the low-pass images (allocation-free rule).
static __device__ float g_lowA[BMAX * PLANE];
static __device__ float g_lowB[BMAX * PLANE];

__device__ __forceinline__ int refl(int i) {
    // jnp.pad 'symmetric': -1 -> 0, -2 -> 1, N -> N-1
    if (i < 0)   i = -1 - i;
    if (i >= HW) i = 2 * HW - 1 - i;
    return i;
}

__device__ __forceinline__ float4 rev4(float4 v) {
    float4 r; r.x = v.w; r.y = v.z; r.z = v.y; r.w = v.x; return r;
}

// Load f4 column tc (may be in [-4, 259]) of a row, with symmetric x-reflection.
// f4 col -k maps to reversed f4 col k-1; col 256+k to reversed col 255-k.
__device__ __forceinline__ float4 ldtap(const float* __restrict__ rb, int tc) {
    bool rv = false;
    if (tc < 0)        { tc = -1 - tc;  rv = true; }
    else if (tc > 255) { tc = 511 - tc; rv = true; }
    const float4 v = *reinterpret_cast<const float4*>(rb + 4 * tc);
    return rv ? rev4(v) : v;
}

__device__ __forceinline__ float4 vcomb5(const float4& a, const float4& b,
                                         const float4& c, const float4& d,
                                         const float4& e) {
    float4 v;
    v.x = CW0 * (a.x + e.x) + CW1 * (b.x + d.x) + CW2 * c.x;
    v.y = CW0 * (a.y + e.y) + CW1 * (b.y + d.y) + CW2 * c.y;
    v.z = CW0 * (a.z + e.z) + CW1 * (b.z + d.z) + CW2 * c.z;
    v.w = CW0 * (a.w + e.w) + CW1 * (b.w + d.w) + CW2 * c.w;
    return v;
}

// One starlet scale, horizontal-first / smem-free / barrier-free.
// Vertical dilated-by-D conv == plain 5-tap on each of D row-subsampled
// sub-images. Block = 256 threads = one full 1024-float row of f4 columns.
// Each thread: horizontal 5-tap from global (tap loads are L1 hits of
// neighboring lanes' lines), then a 4-deep register sliding window of
// h-values gives the vertical conv. Raw centers ride a 2-deep pipeline.
template<int D, int SRC, int DST>
__global__ __launch_bounds__(256, 4)
void starlet_hfirst(const float* __restrict__ ext_in,
                    const float* __restrict__ norms,
                    int scale,
                    float* __restrict__ coeff_out)
{
    constexpr int S = 32;   // sub-rows per block

    const int t     = threadIdx.x;       // f4 column 0..255
    const int resid = blockIdx.y;        // residue class
    const int s0    = blockIdx.x * S;    // first sub-row of strip
    const int b     = blockIdx.z;

    const float* src  = (SRC == 0) ? ext_in : (SRC == 1 ? g_lowA : g_lowB);
    const float* simg = src + (size_t)b * PLANE;
    float* lowdst = (DST == 1) ? g_lowA : (DST == 2 ? g_lowB : nullptr);
    if (DST != 0) lowdst += (size_t)b * PLANE;

    const float  inv  = 1.0f / norms[scale];
    const size_t step = (size_t)D * HW;

    // Horizontal 5-tap of one row (given row base); also returns raw center f4.
    auto hrow = [&](const float* rb, float4& raw) -> float4 {
        if constexpr (D >= 4) {
            constexpr int G1 = D / 4;    // tap at +-D floats  = +-G1 f4
            constexpr int G2 = D / 2;    // tap at +-2D floats = +-G2 f4
            const float4 A  = ldtap(rb, t - G2);
            const float4 Bv = ldtap(rb, t - G1);
            const float4 C  = *reinterpret_cast<const float4*>(rb + 4 * t);
            const float4 Dv = ldtap(rb, t + G1);
            const float4 E  = ldtap(rb, t + G2);
            raw = C;
            return vcomb5(A, Bv, C, Dv, E);
        } else {
            float fl[12];
            *reinterpret_cast<float4*>(&fl[0]) = ldtap(rb, t - 1);
            const float4 C = *reinterpret_cast<const float4*>(rb + 4 * t);
            *reinterpret_cast<float4*>(&fl[4]) = C;
            *reinterpret_cast<float4*>(&fl[8]) = ldtap(rb, t + 1);
            raw = C;
            float4 h;
            h.x = CW0 * (fl[4 - 2*D] + fl[4 + 2*D]) + CW1 * (fl[4 - D] + fl[4 + D]) + CW2 * fl[4];
            h.y = CW0 * (fl[5 - 2*D] + fl[5 + 2*D]) + CW1 * (fl[5 - D] + fl[5 + D]) + CW2 * fl[5];
            h.z = CW0 * (fl[6 - 2*D] + fl[6 + 2*D]) + CW1 * (fl[6 - D] + fl[6 + D]) + CW2 * fl[6];
            h.w = CW0 * (fl[7 - 2*D] + fl[7 + 2*D]) + CW1 * (fl[7 - D] + fl[7 + D]) + CW2 * fl[7];
            return h;
        }
    };

    // nb() yields row-base pointers for sub-rows s0-2, s0-1, ... in order.
    auto run = [&](auto&& nb) {
        float4 dump;
        float4 hm0 = hrow(nb(), dump);
        float4 hm1 = hrow(nb(), dump);
        float4 hm2 = hrow(nb(), dump);   // raw of this row unused (centers start at s0)
        float4 rc0, rc1;
        // careful: raw center pipeline must hold rows s0 and s0+1
        // hm2 corresponds to row s0; recompute its raw via its center load:
        // cheaper: re-derive by calling hrow with raw refs on rows s0, s0+1.
        hm2 = hm2; // (raw for s0 captured below)
        // Instead, prime with raw capture on the last two rows:
        // rows loaded so far: s0-2, s0-1, s0(dump). Load s0+1 with raw:
        float4 hm3 = hrow(nb(), rc1);
        // rc0 (row s0) was dumped above; re-read just the center f4 of row s0:
        // row s0 base = current position - 1 step relative to nb sequence is
        // not retrievable generically; so instead capture it properly below.
        (void)rc1;

        // --- proper priming (redo cleanly) ---
        // NOTE: the above is replaced by the loop below using rcap flags.
        float* cp = coeff_out + ((size_t)b * HW + (size_t)(resid + D * s0)) * HW + 4 * t;
        float* lp = (DST != 0) ? lowdst + (size_t)(resid + D * s0) * HW + 4 * t : nullptr;

        #pragma unroll 2
        for (int s = 0; s < S; s++) {
            float4 rnew;
            const float4 hn  = hrow(nb(), rnew);            // row s0+s+2
            const float4 low = vcomb5(hm0, hm1, hm2, hm3, hn);

            float4 cf;
            cf.x = (rc0.x - low.x) * inv;
            cf.y = (rc0.y - low.y) * inv;
            cf.z = (rc0.z - low.z) * inv;
            cf.w = (rc0.w - low.w) * inv;

            __stcs(reinterpret_cast<float4*>(cp), cf);      // streaming store
            cp += step;
            if (DST != 0) {
                *reinterpret_cast<float4*>(lp) = low;
                lp += step;
            }

            hm0 = hm1; hm1 = hm2; hm2 = hm3; hm3 = hn;
            rc0 = rc1; rc1 = rnew;
        }
    };

    // Priming needs raw centers of rows s0 and s0+1 -> do priming explicitly
    // here instead of inside run() (see wrapper below).
    const int HWsub = HW / D;
    if (s0 >= 2 && s0 + S + 2 <= HWsub) {
        const float* p = simg + (size_t)(resid + D * (s0 - 2)) * HW;
        auto nb = [&]() -> const float* { const float* r = p; p += step; return r; };
        // explicit priming with correct raw capture:
        float4 dump, rc0, rc1;
        float4 hm0 = hrow(nb(), dump);
        float4 hm1 = hrow(nb(), dump);
        float4 hm2 = hrow(nb(), rc0);    // row s0
        float4 hm3 = hrow(nb(), rc1);    // row s0+1
        float* cp = coeff_out + ((size_t)b * HW + (size_t)(resid + D * s0)) * HW + 4 * t;
        float* lp = (DST != 0) ? lowdst + (size_t)(resid + D * s0) * HW + 4 * t : nullptr;
        #pragma unroll 2
        for (int s = 0; s < S; s++) {
            float4 rnew;
            const float4 hn  = hrow(nb(), rnew);
            const float4 low = vcomb5(hm0, hm1, hm2, hm3, hn);
            float4 cf;
            cf.x = (rc0.x - low.x) * inv;
            cf.y = (rc0.y - low.y) * inv;
            cf.z = (rc0.z - low.z) * inv;
            cf.w = (rc0.w - low.w) * inv;
            __stcs(reinterpret_cast<float4*>(cp), cf);
            cp += step;
            if (DST != 0) { *reinterpret_cast<float4*>(lp) = low; lp += step; }
            hm0 = hm1; hm1 = hm2; hm2 = hm3; hm3 = hn;
            rc0 = rc1; rc1 = rnew;
        }
    } else {
        int srow = s0 - 2;
        auto nb = [&]() -> const float* {
            const int f = refl(resid + D * srow);
            srow++;
            return simg + (size_t)f * HW;
        };
        float4 dump, rc0, rc1;
        float4 hm0 = hrow(nb(), dump);
        float4 hm1 = hrow(nb(), dump);
        float4 hm2 = hrow(nb(), rc0);    // row s0
        float4 hm3 = hrow(nb(), rc1);    // row s0+1
        float* cp = coeff_out + ((size_t)b * HW + (size_t)(resid + D * s0)) * HW + 4 * t;
        float* lp = (DST != 0) ? lowdst + (size_t)(resid + D * s0) * HW + 4 * t : nullptr;
        #pragma unroll 2
        for (int s = 0; s < S; s++) {
            float4 rnew;
            const float4 hn  = hrow(nb(), rnew);
            const float4 low = vcomb5(hm0, hm1, hm2, hm3, hn);
            float4 cf;
            cf.x = (rc0.x - low.x) * inv;
            cf.y = (rc0.y - low.y) * inv;
            cf.z = (rc0.z - low.z) * inv;
            cf.w = (rc0.w - low.w) * inv;
            __stcs(reinterpret_cast<float4*>(cp), cf);
            cp += step;
            if (DST != 0) { *reinterpret_cast<float4*>(lp) = low; lp += step; }
            hm0 = hm1; hm1 = hm2; hm2 = hm3; hm3 = hn;
            rc0 = rc1; rc1 = rnew;
        }
    }
    (void)run;  // run() kept unused; explicit paths above are authoritative
}

extern "C" void kernel_launch(void* const* d_in, const int* in_sizes, int n_in,
                              void* d_out, int out_size)
{
    int img_idx = 0, nrm_idx = 1;
    if (n_in >= 2 && in_sizes[0] == 4) { img_idx = 1; nrm_idx = 0; }

    const float* image = (const float*)d_in[img_idx];
    const float* norms = (const float*)d_in[nrm_idx];
    float* out = (float*)d_out;

    int B = in_sizes[img_idx] / PLANE;
    if (B < 1) B = 1;
    if (B > BMAX) B = BMAX;
    const size_t plane_all = (size_t)B * PLANE;

    const dim3 block(256);
    // grid: x = strips of 32 sub-rows, y = D residues, z = batch (512 blocks/scale)
    const dim3 g1(HW / (1 * 32), 1, B);
    const dim3 g2(HW / (2 * 32), 2, B);
    const dim3 g4(HW / (4 * 32), 4, B);
    const dim3 g8(HW / (8 * 32), 8, B);

    starlet_hfirst<1, 0, 1><<<g1, block>>>(image, norms, 0, out + 0 * plane_all);
    starlet_hfirst<2, 1, 2><<<g2, block>>>(image, norms, 1, out + 1 * plane_all);
    starlet_hfirst<4, 2, 1><<<g4, block>>>(image, norms, 2, out + 2 * plane_all);
    starlet_hfirst<8, 1, 0><<<g8, block>>>(image, norms, 3, out + 3 * plane_all);
}

// round 10
// speedup vs baseline: 1.1128x; 1.1128x over previous
#include <cuda_runtime.h>
#include <cstdint>

#define HW 1024
#define PLANE (HW * HW)
#define BMAX 16

// Intermediate low-pass (after scale 1) between the two fused kernels.
static __device__ float g_low[BMAX * PLANE];

static constexpr float CW0 = 1.0f / 16.0f;
static constexpr float CW1 = 1.0f / 4.0f;
static constexpr float CW2 = 3.0f / 8.0f;

__device__ __forceinline__ int refl(int i) {
    // jnp.pad 'symmetric': -1 -> 0, -2 -> 1, N -> N-1
    if (i < 0)   i = -1 - i;
    if (i >= HW) i = 2 * HW - 1 - i;
    return i;
}

__device__ __forceinline__ float4 rev4(const float4 v) {
    float4 r; r.x = v.w; r.y = v.z; r.z = v.y; r.w = v.x; return r;
}

__device__ __forceinline__ float4 vcomb5(const float4& a, const float4& b,
                                         const float4& c, const float4& d,
                                         const float4& e) {
    float4 v;
    v.x = CW0 * (a.x + e.x) + CW1 * (b.x + d.x) + CW2 * c.x;
    v.y = CW0 * (a.y + e.y) + CW1 * (b.y + d.y) + CW2 * c.y;
    v.z = CW0 * (a.z + e.z) + CW1 * (b.z + d.z) + CW2 * c.z;
    v.w = CW0 * (a.w + e.w) + CW1 * (b.w + d.w) + CW2 * c.w;
    return v;
}

__device__ __forceinline__ float4 cmul(const float4& a, const float4& b, float s) {
    float4 r;
    r.x = (a.x - b.x) * s; r.y = (a.y - b.y) * s;
    r.z = (a.z - b.z) * s; r.w = (a.w - b.w) * s;
    return r;
}

// f4-column tap from an smem row (1024 valid floats), symmetric x-reflection:
// f4 col -k == reversed col k-1;  col 256+k == reversed col 255-k.
__device__ __forceinline__ float4 smtap(const float* __restrict__ row, int tc) {
    bool rv = false;
    if (tc < 0)        { tc = -1 - tc;  rv = true; }
    else if (tc > 255) { tc = 511 - tc; rv = true; }
    const float4 v = *reinterpret_cast<const float4*>(row + 4 * tc);
    return rv ? rev4(v) : v;
}

// Horizontal 5-tap with dilation DH floats; center f4 supplied in registers.
template<int DH>
__device__ __forceinline__ float4 hconv(const float* __restrict__ row, int t,
                                        const float4& c) {
    if constexpr (DH < 4) {
        float fl[12];
        *reinterpret_cast<float4*>(&fl[0]) = smtap(row, t - 1);
        fl[4] = c.x; fl[5] = c.y; fl[6] = c.z; fl[7] = c.w;
        *reinterpret_cast<float4*>(&fl[8]) = smtap(row, t + 1);
        float4 h;
        h.x = CW0 * (fl[4 - 2*DH] + fl[4 + 2*DH]) + CW1 * (fl[4 - DH] + fl[4 + DH]) + CW2 * fl[4];
        h.y = CW0 * (fl[5 - 2*DH] + fl[5 + 2*DH]) + CW1 * (fl[5 - DH] + fl[5 + DH]) + CW2 * fl[5];
        h.z = CW0 * (fl[6 - 2*DH] + fl[6 + 2*DH]) + CW1 * (fl[6 - DH] + fl[6 + DH]) + CW2 * fl[6];
        h.w = CW0 * (fl[7 - 2*DH] + fl[7 + 2*DH]) + CW1 * (fl[7 - DH] + fl[7 + DH]) + CW2 * fl[7];
        return h;
    } else {
        constexpr int G = DH / 4;
        const float4 A  = smtap(row, t - 2 * G);
        const float4 Bv = smtap(row, t - G);
        const float4 Dv = smtap(row, t + G);
        const float4 E  = smtap(row, t + 2 * G);
        return vcomb5(A, Bv, c, Dv, E);
    }
}

// Fused pair of starlet scales (dilations D and 2D).
// Block = 256 threads = one full 1024-float row; blockIdx.y = residue mod D;
// blockIdx.x = strip of S sub-rows; blockIdx.z = batch.
// Stream sub-row positions p = s0-4 .. s0+S+3 (overhang feeds the lag-4
// second-scale pipeline). Per position: raw register window -> v2 -> smem ->
// h2 -> low_k (coeff_k out). low_k values feed two 5-deep parity chains
// (spacing 2 positions = dilation 2D vertical conv) -> v3 -> smem -> h3 ->
// low_{k+1} (coeff_{k+1} out, optional low write).
template<int D, bool EXT, bool WLOW>
__global__ __launch_bounds__(256, 3)
void starlet_pair(const float* __restrict__ ext_in,
                  const float* __restrict__ norms, int k,
                  float* __restrict__ c2, float* __restrict__ c3)
{
    constexpr int S = 32;
    constexpr int NSLAB = (S + 8) / 2;   // 20 slabs, 2 positions each

    __shared__ __align__(16) float sm[4][HW + 4];

    const int t     = threadIdx.x;
    const int resid = blockIdx.y;
    const int s0    = blockIdx.x * S;
    const int b     = blockIdx.z;
    const int x4    = 4 * t;

    const float* simg = (EXT ? ext_in : g_low) + (size_t)b * PLANE;
    float* lowp = WLOW ? (g_low + (size_t)b * PLANE) : nullptr;
    const float inv2 = 1.0f / norms[k];
    const float inv3 = 1.0f / norms[k + 1];
    const size_t step   = (size_t)D * HW;
    const size_t bplane = (size_t)b * PLANE;

    auto run = [&](auto&& ldnext) {
        // raw window: w0..w3 = positions p-2..p+1, n0,n1 = p+2,p+3 (p = s0-4)
        float4 w0 = ldnext(), w1 = ldnext(), w2 = ldnext(), w3 = ldnext();
        float4 n0 = ldnext(), n1 = ldnext();
        const float4 z = make_float4(0.f, 0.f, 0.f, 0.f);
        // parity chains of low_k values (even positions: e*, odd: o*)
        float4 e1 = z, e2 = z, e3 = z, e4 = z;
        float4 o1 = z, o2 = z, o3 = z, o4 = z;

        #pragma unroll 5
        for (int i = 0; i < NSLAB; i++) {
            // ---- scale-k vertical for positions p = s0-4+2i, p+1 ----
            const float4 v2A = vcomb5(w0, w1, w2, w3, n0);
            const float4 v2B = vcomb5(w1, w2, w3, n0, n1);
            *reinterpret_cast<float4*>(&sm[0][x4]) = v2A;
            *reinterpret_cast<float4*>(&sm[1][x4]) = v2B;
            // shift window; raw centers at p,p+1 are now w0,w1
            w0 = w2; w1 = w3; w2 = n0; w3 = n1;
            if (i + 1 < NSLAB) { n0 = ldnext(); n1 = ldnext(); }
            __syncthreads();

            // ---- scale-k horizontal -> low_k; emit coeff_k if in range ----
            const float4 l2A = hconv<D>(sm[0], t, v2A);
            const float4 l2B = hconv<D>(sm[1], t, v2B);
            if (i >= 2 && i <= NSLAB - 3) {
                const int y = resid + D * (s0 - 4 + 2 * i);
                float* p2 = c2 + bplane + (size_t)y * HW + x4;
                __stcs(reinterpret_cast<float4*>(p2),        cmul(w0, l2A, inv2));
                __stcs(reinterpret_cast<float4*>(p2 + step), cmul(w1, l2B, inv2));
            }

            // ---- scale-(k+1) vertical from parity chains (lag 4 positions) ----
            const bool emit3 = (i >= 4);
            if (emit3) {
                const float4 v3E = vcomb5(e1, e2, e3, e4, l2A);   // center p-4
                const float4 v3O = vcomb5(o1, o2, o3, o4, l2B);   // center p-3
                *reinterpret_cast<float4*>(&sm[2][x4]) = v3E;
                *reinterpret_cast<float4*>(&sm[3][x4]) = v3O;
            }
            e1 = e2; e2 = e3; e3 = e4; e4 = l2A;   // post-shift: e2 = low_k at p-4
            o1 = o2; o2 = o3; o3 = o4; o4 = l2B;   //             o2 = low_k at p-3
            __syncthreads();

            if (emit3) {
                // own v3 re-read from smem (saves registers)
                const float4 c3E = *reinterpret_cast<const float4*>(&sm[2][x4]);
                const float4 c3O = *reinterpret_cast<const float4*>(&sm[3][x4]);
                const float4 l3E = hconv<2 * D>(sm[2], t, c3E);
                const float4 l3O = hconv<2 * D>(sm[3], t, c3O);
                const int yq = resid + D * (s0 - 8 + 2 * i);      // row of pos p-4
                float* p3 = c3 + bplane + (size_t)yq * HW + x4;
                __stcs(reinterpret_cast<float4*>(p3),        cmul(e2, l3E, inv3));
                __stcs(reinterpret_cast<float4*>(p3 + step), cmul(o2, l3O, inv3));
                if constexpr (WLOW) {
                    float* lp = lowp + (size_t)yq * HW + x4;
                    *reinterpret_cast<float4*>(lp)        = l3E;
                    *reinterpret_cast<float4*>(lp + step) = l3O;
                }
            }
        }
    };

    const int HWsub = HW / D;
    if (s0 >= 6 && s0 + S + 5 < HWsub) {
        // interior strip: incremental pointer, no reflection possible
        const float* p = simg + (size_t)(resid + D * (s0 - 6)) * HW + x4;
        run([&]() -> float4 {
            const float4 v = *reinterpret_cast<const float4*>(p);
            p += step;
            return v;
        });
    } else {
        // boundary strip: reflected full-image row per stream position
        int s = s0 - 6;
        run([&]() -> float4 {
            const int f = refl(resid + D * s);
            s++;
            return *reinterpret_cast<const float4*>(simg + (size_t)f * HW + x4);
        });
    }
}

extern "C" void kernel_launch(void* const* d_in, const int* in_sizes, int n_in,
                              void* d_out, int out_size)
{
    int img_idx = 0, nrm_idx = 1;
    if (n_in >= 2 && in_sizes[0] == 4) { img_idx = 1; nrm_idx = 0; }

    const float* image = (const float*)d_in[img_idx];
    const float* norms = (const float*)d_in[nrm_idx];
    float* out = (float*)d_out;

    int B = in_sizes[img_idx] / PLANE;
    if (B < 1) B = 1;
    if (B > BMAX) B = BMAX;
    const size_t plane_all = (size_t)B * PLANE;

    const dim3 blk(256);
    // K01: scales 0,1 (dilations 1,2) from image; writes coeff0, coeff1, low1.
    const dim3 gA(HW / 32, 1, B);          // 512 blocks
    // K23: scales 2,3 (dilations 4,8) from low1; writes coeff2, coeff3.
    const dim3 gB(HW / (4 * 32), 4, B);    // 512 blocks

    starlet_pair<1, true,  true ><<<gA, blk>>>(image, norms, 0,
                                               out, out + plane_all);
    starlet_pair<4, false, false><<<gB, blk>>>(image, norms, 2,
                                               out + 2 * plane_all,
                                               out + 3 * plane_all);
}

// round 11
// speedup vs baseline: 1.2149x; 1.0918x over previous
#include <cuda_runtime.h>
#include <cstdint>

#define HW 1024
#define PLANE (HW * HW)
#define BMAX 16

// Ping-pong scratch for the low-pass images (allocation-free rule).
static __device__ float g_lowA[BMAX * PLANE];
static __device__ float g_lowB[BMAX * PLANE];

__device__ __forceinline__ int refl(int i) {
    // jnp.pad 'symmetric': -1 -> 0, -2 -> 1, N -> N-1
    if (i < 0)   i = -1 - i;
    if (i >= HW) i = 2 * HW - 1 - i;
    return i;
}

// One starlet scale. Vertical dilated-by-D conv == plain 5-tap conv on each of
// D row-subsampled sub-images. Block = 256 threads = one full 1024-float row.
// blockIdx.y = residue class, blockIdx.x = strip of S sub-rows, blockIdx.z = batch.
//
// R=2 slabs; vertical results v0,v1 stay in registers across the barrier and
// serve as the horizontal center tap. DEPTH-2 prefetch: the two LDG.128 for
// slab k+2 are issued at the top of iteration k, giving every load ~2 slabs
// of latency slack. Addressing via uint32 plane offsets (bases UR-promoted).
template<int D, int SRC, int DST>
__global__ __launch_bounds__(256, 4)
void starlet_stream(const float* __restrict__ ext_in,
                    const float* __restrict__ norms,
                    int scale,
                    float* __restrict__ coeff_out)
{
    constexpr int S = 32;     // sub-rows per block
    constexpr int NSLAB = S / 2;
    constexpr float W0 = 1.0f / 16.0f;
    constexpr float W1 = 1.0f / 4.0f;
    constexpr float W2 = 3.0f / 8.0f;

    __shared__ __align__(16) float sm[2][2][HW + 4];

    const int t     = threadIdx.x;        // float4 column 0..255
    const int resid = blockIdx.y;         // residue class
    const int s0    = blockIdx.x * S;     // first sub-row of strip
    const int b     = blockIdx.z;

    const float* src  = (SRC == 0) ? ext_in : (SRC == 1 ? g_lowA : g_lowB);
    const float* simg = src + (size_t)b * PLANE;
    const float* cbase = coeff_out + (size_t)b * PLANE;   // loop-invariant
    const float* lbase = ((DST == 1) ? g_lowA : g_lowB) + (size_t)b * PLANE;

    const int x4 = 4 * t;
    const float inv = 1.0f / norms[scale];
    const uint32_t stepu = (uint32_t)(D * HW);   // floats between sub-rows

    auto vcomb = [&](const float4& a, const float4& bb, const float4& c,
                     const float4& d, const float4& e) -> float4 {
        float4 v;
        v.x = W0 * (a.x + e.x) + W1 * (bb.x + d.x) + W2 * c.x;
        v.y = W0 * (a.y + e.y) + W1 * (bb.y + d.y) + W2 * c.y;
        v.z = W0 * (a.z + e.z) + W1 * (bb.z + d.z) + W2 * c.z;
        v.w = W0 * (a.w + e.w) + W1 * (bb.w + d.w) + W2 * c.w;
        return v;
    };

    // Body, parameterized on a sequential row loader (returns sub-rows
    // s0-2, s0-1, s0, ... in order; exactly S+4 calls).
    auto run = [&](auto&& ldnext) {
        // w0..w3 = rows base-2..base+1; n0,n1 = base+2,+3; f0,f1 = base+4,+5
        float4 w0 = ldnext(), w1 = ldnext(), w2 = ldnext(), w3 = ldnext();
        float4 n0 = ldnext(), n1 = ldnext();
        float4 f0 = ldnext(), f1 = ldnext();

        uint32_t off = (uint32_t)((resid + D * s0) * HW + x4);

        #pragma unroll 4
        for (int slab = 0; slab < NSLAB; slab++) {
            const int buf = slab & 1;

            // ---- depth-2 prefetch: rows base+6, base+7 (consumed at slab+2) ----
            float4 g0 = {}, g1 = {};
            const bool more = (slab + 2 < NSLAB);
            if (more) { g0 = ldnext(); g1 = ldnext(); }

            // ---- vertical 5-tap; results stay in regs as horizontal centers ----
            const float4 v0 = vcomb(w0, w1, w2, w3, n0);
            const float4 v1 = vcomb(w1, w2, w3, n0, n1);
            *reinterpret_cast<float4*>(&sm[buf][0][x4]) = v0;
            *reinterpret_cast<float4*>(&sm[buf][1][x4]) = v1;

            // shift window (raw centers become new w0,w1)
            w0 = w2; w1 = w3; w2 = n0; w3 = n1; n0 = f0; n1 = f1;
            if (more) { f0 = g0; f1 = g1; }

            __syncthreads();

            // ---- horizontal 5-tap (dilated by D along x), center from register ----
            #pragma unroll
            for (int r = 0; r < 2; r++) {
                const float4 vc  = (r == 0) ? v0 : v1;
                const float4 raw = (r == 0) ? w0 : w1;
                float4 low;

                if constexpr (D >= 4) {
                    constexpr int G = D / 4;           // tap offset in f4 groups
                    if (t >= 2 * G && t <= 255 - 2 * G) {
                        const float4 a  = *reinterpret_cast<const float4*>(&sm[buf][r][x4 - 8 * G]);
                        const float4 bb = *reinterpret_cast<const float4*>(&sm[buf][r][x4 - 4 * G]);
                        const float4 d  = *reinterpret_cast<const float4*>(&sm[buf][r][x4 + 4 * G]);
                        const float4 e  = *reinterpret_cast<const float4*>(&sm[buf][r][x4 + 8 * G]);
                        low = vcomb(a, bb, vc, d, e);
                    } else {
                        float lo[4];
                        #pragma unroll
                        for (int j = 0; j < 4; j++) {
                            const int e0 = x4 + j;
                            auto g = [&](int m) -> float {
                                int e = e0 + m;
                                if (e < 0)   e = -1 - e;
                                if (e >= HW) e = 2 * HW - 1 - e;
                                return sm[buf][r][e];
                            };
                            lo[j] = W0 * (g(-2 * D) + g(2 * D))
                                  + W1 * (g(-D) + g(D)) + W2 * g(0);
                        }
                        low.x = lo[0]; low.y = lo[1]; low.z = lo[2]; low.w = lo[3];
                    }
                } else {
                    if (t >= 1 && t <= 254) {
                        float fl[12];
                        *reinterpret_cast<float4*>(&fl[0]) = *reinterpret_cast<const float4*>(&sm[buf][r][x4 - 4]);
                        fl[4] = vc.x; fl[5] = vc.y; fl[6] = vc.z; fl[7] = vc.w;
                        *reinterpret_cast<float4*>(&fl[8]) = *reinterpret_cast<const float4*>(&sm[buf][r][x4 + 4]);
                        float lo[4];
                        #pragma unroll
                        for (int j = 0; j < 4; j++) {
                            lo[j] = W0 * (fl[4 + j - 2 * D] + fl[4 + j + 2 * D])
                                  + W1 * (fl[4 + j - D]     + fl[4 + j + D])
                                  + W2 *  fl[4 + j];
                        }
                        low.x = lo[0]; low.y = lo[1]; low.z = lo[2]; low.w = lo[3];
                    } else {
                        float lo[4];
                        #pragma unroll
                        for (int j = 0; j < 4; j++) {
                            const int e0 = x4 + j;
                            auto g = [&](int m) -> float {
                                int e = e0 + m;
                                if (e < 0)   e = -1 - e;
                                if (e >= HW) e = 2 * HW - 1 - e;
                                return sm[buf][r][e];
                            };
                            lo[j] = W0 * (g(-2 * D) + g(2 * D))
                                  + W1 * (g(-D) + g(D)) + W2 * g(0);
                        }
                        low.x = lo[0]; low.y = lo[1]; low.z = lo[2]; low.w = lo[3];
                    }
                }

                float4 cf;
                cf.x = (raw.x - low.x) * inv;
                cf.y = (raw.y - low.y) * inv;
                cf.z = (raw.z - low.z) * inv;
                cf.w = (raw.w - low.w) * inv;

                __stcs((float4*)(cbase + off), cf);            // streaming store
                if (DST != 0) {
                    *(float4*)(lbase + off) = low;             // keep in L2
                }
                off += stepu;
            }
            // double-buffered smem: no trailing barrier
        }
    };

    const int HWsub = HW / D;   // sub-image height
    if (s0 >= 2 && s0 + S + 2 <= HWsub) {
        // interior strip: pure incremental offset, no reflection possible
        uint32_t roff = (uint32_t)((resid + D * (s0 - 2)) * HW + x4);
        run([&]() -> float4 {
            const float4 v = *reinterpret_cast<const float4*>(simg + roff);
            roff += stepu;
            return v;
        });
    } else {
        // boundary strip: reflected row indices
        int s = s0 - 2;
        run([&]() -> float4 {
            const int f = refl(resid + D * s);
            s++;
            return *reinterpret_cast<const float4*>(simg + (size_t)f * HW + x4);
        });
    }
}

extern "C" void kernel_launch(void* const* d_in, const int* in_sizes, int n_in,
                              void* d_out, int out_size)
{
    int img_idx = 0, nrm_idx = 1;
    if (n_in >= 2 && in_sizes[0] == 4) { img_idx = 1; nrm_idx = 0; }

    const float* image = (const float*)d_in[img_idx];
    const float* norms = (const float*)d_in[nrm_idx];
    float* out = (float*)d_out;

    int B = in_sizes[img_idx] / PLANE;
    if (B < 1) B = 1;
    if (B > BMAX) B = BMAX;
    const size_t plane_all = (size_t)B * PLANE;

    const dim3 block(256);
    // grid: x = strips of 32 sub-rows, y = D residues, z = batch (512 blocks/scale)
    const dim3 g1(HW / (1 * 32), 1, B);
    const dim3 g2(HW / (2 * 32), 2, B);
    const dim3 g4(HW / (4 * 32), 4, B);
    const dim3 g8(HW / (8 * 32), 8, B);

    starlet_stream<1, 0, 1><<<g1, block>>>(image, norms, 0, out + 0 * plane_all);
    starlet_stream<2, 1, 2><<<g2, block>>>(image, norms, 1, out + 1 * plane_all);
    starlet_stream<4, 2, 1><<<g4, block>>>(image, norms, 2, out + 2 * plane_all);
    starlet_stream<8, 1, 0><<<g8, block>>>(image, norms, 3, out + 3 * plane_all);
}